// round 16
// baseline (speedup 1.0000x reference)
#include <cuda_runtime.h>
#include <cuda_fp16.h>
#include <cstdint>

#define BB 8
#define CC_ 128
#define HH 192
#define WW 192
#define HW (HH*WW)
#define CHW (CC_*HW)
#define TOT (BB*CHW)
#define KK 1152            // C*9
#define EPSV 1e-5f
#define NORM_SCALE 0.1816f
#define STAT_N (BB*4*(HH/2)*(WW/2))   // 294912

// padded image geometry (1-px halo + alignment tail)
#define WP 200
#define HP 194
#define PLANE (HP*WP)          // 38800
#define PCHW (CC_*PLANE)
#define PTOT (BB*PCHW)

// ---------------- scratch (device globals; no allocations allowed) ------------
__device__ __align__(16) __half g_pxe[PTOT];     // input, aligned shift (dx 0/2)
__device__ __align__(16) __half g_pxo[PTOT];     // input, odd shift (dx 1)
__device__ __align__(16) __half g_pae[PTOT];     // a3, aligned
__device__ __align__(16) __half g_pao[PTOT];     // a3, odd
// parity-packed conv outputs: [b][ch][class(9)][4096]
__device__ __align__(16) __half g_a1p[TOT];
__device__ __align__(16) __half g_a2p[TOT];
__device__ float g_av[TOT];
__device__ __align__(16) __half g_w[3*CC_*KK];   // [w][o][knew], knew=(r*3+dx)*128+ic
__device__ __align__(16) __half g_k[BB*CC_*KK];  // [b][o][knew]
__device__ float g_attn[BB*CC_*KK];        // [b][o][i*9+class]
__device__ float g_sum[CC_];
__device__ float g_sumsq[CC_];
__device__ float g_mean[CC_];
__device__ float g_inv[CC_];

// ---------------- PTX helpers -------------------------------------------------
__device__ __forceinline__ uint32_t smem_u32(const void* p) {
    uint32_t a;
    asm("{ .reg .u64 t; cvta.to.shared.u64 t, %1; cvt.u32.u64 %0, t; }"
        : "=r"(a) : "l"(p));
    return a;
}
__device__ __forceinline__ void ldsm4(unsigned* r, uint32_t addr) {
    asm volatile("ldmatrix.sync.aligned.m8n8.x4.shared.b16 {%0,%1,%2,%3}, [%4];"
                 : "=r"(r[0]), "=r"(r[1]), "=r"(r[2]), "=r"(r[3]) : "r"(addr));
}
__device__ __forceinline__ void ldsm4t(unsigned* r, uint32_t addr) {
    asm volatile("ldmatrix.sync.aligned.m8n8.x4.trans.shared.b16 {%0,%1,%2,%3}, [%4];"
                 : "=r"(r[0]), "=r"(r[1]), "=r"(r[2]), "=r"(r[3]) : "r"(addr));
}
__device__ __forceinline__ void mma_f16(float* d, const unsigned* a, const unsigned* b) {
    asm volatile(
        "mma.sync.aligned.m16n8k16.row.col.f32.f16.f16.f32 "
        "{%0,%1,%2,%3}, {%4,%5,%6,%7}, {%8,%9}, {%0,%1,%2,%3};"
        : "+f"(d[0]), "+f"(d[1]), "+f"(d[2]), "+f"(d[3])
        : "r"(a[0]), "r"(a[1]), "r"(a[2]), "r"(a[3]), "r"(b[0]), "r"(b[1]));
}
__device__ __forceinline__ void mma_f16_2(float* d, const unsigned* a,
                                          unsigned b0, unsigned b1) {
    asm volatile(
        "mma.sync.aligned.m16n8k16.row.col.f32.f16.f16.f32 "
        "{%0,%1,%2,%3}, {%4,%5,%6,%7}, {%8,%9}, {%0,%1,%2,%3};"
        : "+f"(d[0]), "+f"(d[1]), "+f"(d[2]), "+f"(d[3])
        : "r"(a[0]), "r"(a[1]), "r"(a[2]), "r"(a[3]), "r"(b0), "r"(b1));
}
__device__ __forceinline__ void cp16(uint32_t dst, const void* src) {
    asm volatile("cp.async.cg.shared.global [%0], [%1], 16;"
                 :: "r"(dst), "l"(src) : "memory");
}
__device__ __forceinline__ void cp4(uint32_t dst, const void* src) {
    asm volatile("cp.async.ca.shared.global [%0], [%1], 4;"
                 :: "r"(dst), "l"(src) : "memory");
}
__device__ __forceinline__ void cp_commit() {
    asm volatile("cp.async.commit_group;" ::: "memory");
}
__device__ __forceinline__ void cp_wait1() {
    asm volatile("cp.async.wait_group 1;" ::: "memory");
}
__device__ __forceinline__ void cp_wait0() {
    asm volatile("cp.async.wait_group 0;" ::: "memory");
}

// ---------------- zero accumulators + padded-array halos ----------------------
__global__ void zero_kernel() {
    int n = BB*CC_*KK;
    for (int i = blockIdx.x*blockDim.x + threadIdx.x; i < n; i += gridDim.x*blockDim.x)
        g_attn[i] = 0.f;
    const __half z = __float2half(0.f);
    int hn = BB*CC_*2128;
    for (int idx = blockIdx.x*blockDim.x + threadIdx.x; idx < hn;
         idx += gridDim.x*blockDim.x) {
        int plane = idx / 2128, e = idx - plane*2128;
        int row, px;
        if (e < 400) { row = (e < 200) ? 0 : 193; px = (e < 200) ? e : e - 200; }
        else { int e2 = e - 400; row = 1 + e2/9; int i9 = e2 - (e2/9)*9;
               px = (i9 < 2) ? i9 : 191 + i9; }
        size_t off = (size_t)plane*PLANE + row*WP + px;
        g_pae[off] = z; g_pao[off] = z;
    }
    if (blockIdx.x == 0 && threadIdx.x < CC_) {
        g_sum[threadIdx.x] = 0.f;
        g_sumsq[threadIdx.x] = 0.f;
    }
}

// ---------------- pad x into fp16 copies (aligned + shifted) ------------------
__global__ void split_x_pad_kernel(const float* __restrict__ x) {
    for (size_t idx = (size_t)blockIdx.x*blockDim.x + threadIdx.x; idx < (size_t)PTOT;
         idx += (size_t)gridDim.x*blockDim.x) {
        size_t bc = idx / PLANE;
        int p  = (int)(idx - bc*PLANE);
        int py = p / WP, px = p - py*WP;
        int yy = py - 1;
        float va = 0.f, vs = 0.f;
        if ((unsigned)yy < HH) {
            const float* row = x + bc*HW + (size_t)yy*WW;
            int xa = px - 1, xs = px - 2;
            if ((unsigned)xa < WW) va = row[xa];
            if ((unsigned)xs < WW) vs = row[xs];
        }
        g_pxe[idx] = __float2half(va);
        g_pxo[idx] = __float2half(vs);
    }
}

// ---------------- convert static weights (permuted k: knew=(r*3+dx)*128+ic) ---
__global__ void split_w_kernel(const float* __restrict__ w1,
                               const float* __restrict__ w2,
                               const float* __restrict__ w3) {
    const float* w = (blockIdx.y == 0) ? w1 : (blockIdx.y == 1) ? w2 : w3;
    int base = blockIdx.y * CC_ * KK;
    for (int e = blockIdx.x*blockDim.x + threadIdx.x; e < CC_*KK;
         e += gridDim.x*blockDim.x) {
        int o = e / KK, knew = e - o*KK;
        int rr = knew >> 7, ic = knew & 127;
        g_w[base + e] = __float2half(w[(size_t)o*KK + ic*9 + rr]);
    }
}

// ---------------- fp16 tensor-core implicit-GEMM 3x3 conv ---------------------
// CTA: M=128 o x N=192 px (full row). 8 warps = 2m x 4n, warp tile m64 x n48.
// K=1152 in 36 chunks of 32, (r,dx)-major. 3-stage cp.async pipeline.
// Modes: 0 fp32 out; 1 padded planes (2 arrays); 2 parity-packed.
#define A_STRIDE 80
#define B_STRIDE 400
#define A_BYTES (128*A_STRIDE)    // 10240
#define B_BYTES (32*B_STRIDE)     // 12800
#define STG (A_BYTES + B_BYTES)   // 23040
#define SMEM_CONV (3*STG)         // 69120

__global__ __launch_bounds__(256, 1) void conv_mma_kernel(
    const __half* __restrict__ pe, const __half* __restrict__ po,
    const __half* __restrict__ w_g, long wbstride,
    void* __restrict__ p0, void* __restrict__ p1, int mode)
{
    extern __shared__ __align__(16) unsigned char smem[];
    const int y = blockIdx.x;
    const int b = blockIdx.y;
    const int tid = threadIdx.x;
    const int lane = tid & 31, wid = tid >> 5;
    const int wm = wid & 1, wn = wid >> 1;   // 2m x 4n
    const uint32_t sb = smem_u32(smem);

    const __half* peb = pe + (size_t)b*PCHW;
    const __half* pob = po + (size_t)b*PCHW;
    const __half* wg = w_g + (size_t)b*wbstride;

    // B fill: 3072 cp4 slots (32 rows x 96 np)
    int bsrc[12], bdst[12];
#pragma unroll
    for (int i = 0; i < 12; i++) {
        int slot = tid + i*256;
        int rowt = slot / 96, np = slot - rowt*96;
        bsrc[i] = rowt*PLANE + np*2;
        bdst[i] = rowt*B_STRIDE + np*4;
    }
    // A fill: 512 cp16 slots
    int adst[2], aoff[2];
#pragma unroll
    for (int i = 0; i < 2; i++) {
        int slot = tid + i*256;
        int o = slot >> 2, qq = slot & 3;
        adst[i] = o*A_STRIDE + qq*16;
        aoff[i] = o*KK + qq*8;
    }

    float acc[4][6][4];
#pragma unroll
    for (int mf = 0; mf < 4; mf++)
#pragma unroll
        for (int j = 0; j < 6; j++)
#pragma unroll
            for (int t = 0; t < 4; t++) acc[mf][j][t] = 0.f;

    auto loadAB = [&](int c) {
        const uint32_t stg = sb + (c % 3)*STG;
        const int kofs = c*32;
#pragma unroll
        for (int i = 0; i < 2; i++) cp16(stg + adst[i], wg + aoff[i] + kofs);
        int r = c / 12, t = c - r*12;
        int dx = t >> 2, q = t & 3;
        int ibase = q*32*PLANE + (y + r)*WP + dx + (dx == 1);
        const __half* hp = ((dx == 1) ? pob : peb) + ibase;
        const uint32_t bb = stg + A_BYTES;
#pragma unroll
        for (int i = 0; i < 12; i++)
            cp4(bb + bdst[i], hp + bsrc[i]);
        cp_commit();
    };

    loadAB(0);
    loadAB(1);

    for (int c = 0; c < 36; c++) {
        if (c < 34) cp_wait1(); else cp_wait0();
        __syncthreads();
        if (c < 34) loadAB(c + 2);

        const uint32_t stg = sb + (c % 3)*STG;
        const uint32_t A_s = stg;
        const uint32_t B_s = stg + A_BYTES;
#pragma unroll
        for (int st = 0; st < 2; st++) {
            unsigned Af[4][4];
#pragma unroll
            for (int mf = 0; mf < 4; mf++) {
                uint32_t off = (uint32_t)(wm*64 + mf*16 + (lane & 15))*A_STRIDE
                             + ((lane >> 4) << 4) + st*32;
                ldsm4(Af[mf], A_s + off);
            }
#pragma unroll
            for (int nf = 0; nf < 3; nf++) {
                unsigned Bf[4];
                uint32_t off = (uint32_t)(st*16 + (lane & 15))*B_STRIDE
                             + wn*96 + nf*32 + ((lane >> 4) << 4);
                ldsm4t(Bf, B_s + off);
#pragma unroll
                for (int mf = 0; mf < 4; mf++) {
#pragma unroll
                    for (int jj = 0; jj < 2; jj++)
                        mma_f16(acc[mf][nf*2 + jj], Af[mf], &Bf[jj*2]);
                }
            }
        }
    }

    // ---- epilogue ----
    if (mode == 0) {
        float* out = (float*)p0;
#pragma unroll
        for (int mf = 0; mf < 4; mf++) {
            int o = wm*64 + mf*16 + (lane >> 2);
#pragma unroll
            for (int j = 0; j < 6; j++) {
                int x = wn*48 + j*8 + (lane & 3)*2;
                size_t i0 = ((size_t)b*CC_ + o)*HW + (size_t)y*WW + x;
                size_t i1 = i0 + (size_t)8*HW;
                *(float2*)(out + i0) = make_float2(acc[mf][j][0], acc[mf][j][1]);
                *(float2*)(out + i1) = make_float2(acc[mf][j][2], acc[mf][j][3]);
            }
        }
    } else if (mode == 1) {
        // stage plane, stride 200 per ch, +1 element shift
        __syncthreads();
        __half* sh = (__half*)smem;      // 128*200
#pragma unroll
        for (int mf = 0; mf < 4; mf++) {
            int o = wm*64 + mf*16 + (lane >> 2);
#pragma unroll
            for (int j = 0; j < 6; j++) {
                int xb = wn*48 + j*8 + (lane & 3)*2;
#pragma unroll
                for (int t = 0; t < 4; t++) {
                    int oo = o + (t >> 1)*8;
                    int xx = xb + (t & 1);
                    sh[oo*200 + xx + 1] = __float2half(acc[mf][j][t]);
                }
            }
        }
        __syncthreads();
        __half* eh = (__half*)p0;   // pae
        __half* oh = (__half*)p1;   // pao
        for (int run = wid; run < 256; run += 8) {
            int a = run >> 7, ch = run & 127;
            const __half* sp = sh + ch*200;
            __half* base = (a == 0) ? eh : oh;
            __half* dst = base + ((size_t)b*CC_ + ch)*PLANE
                        + (size_t)(y + 1)*WP + 1 + a;
            if (a == 0) {
                if (lane == 0) dst[0]   = sp[1];
                if (lane == 1) dst[191] = sp[192];
                for (int j2 = lane; j2 < 95; j2 += 32) {
                    uint32_t v = *(const uint32_t*)(sp + 2 + 2*j2);
                    *(uint32_t*)(dst + 1 + 2*j2) = v;
                }
            } else {
                for (int j2 = lane; j2 < 96; j2 += 32) {
                    uint32_t lo2 = (uint32_t)*(const unsigned short*)(sp + 1 + 2*j2);
                    uint32_t hi2 = (uint32_t)*(const unsigned short*)(sp + 2 + 2*j2);
                    *(uint32_t*)(dst + 2*j2) = lo2 | (hi2 << 16);
                }
            }
        }
    } else {
        // parity-packed: stage [ch][cx*64+qx] plane, then uint4 stores
        __syncthreads();
        __half* sh = (__half*)smem;      // 128*192
#pragma unroll
        for (int mf = 0; mf < 4; mf++) {
            int o = wm*64 + mf*16 + (lane >> 2);
#pragma unroll
            for (int j = 0; j < 6; j++) {
                int xb = wn*48 + j*8 + (lane & 3)*2;
#pragma unroll
                for (int t = 0; t < 4; t++) {
                    int oo = o + (t >> 1)*8;
                    int xx = xb + (t & 1);
                    int qx = xx / 3;
                    int cx = xx - qx*3;
                    sh[oo*192 + cx*64 + qx] = __float2half(acc[mf][j][t]);
                }
            }
        }
        __syncthreads();
        __half* ph = (__half*)p0;
        int cy = y % 3, qy = y / 3;
#pragma unroll
        for (int i = 0; i < 12; i++) {
            int s = tid + i*256;      // < 3072
            int q = s & 7, seg = s >> 3;
            int ch = seg / 3, cx = seg - ch*3;
            const uint4* src = (const uint4*)(sh + ch*192 + cx*64 + q*8);
            __half* dst = ph
                + (((size_t)b*CC_ + ch)*9 + cy*3 + cx)*4096 + qy*64 + q*8;
            *(uint4*)dst = *src;
        }
    }
}

// ---------------- tensor-core attention correlation GEMM ----------------------
// Single fp16 product. M=128(o) x N=128(i), K slab 1024.
#define AT_STRIDE 80
#define AT_BYTES (128*AT_STRIDE)   // 10240
#define AT_STG (2*AT_BYTES)        // 20480
#define SMEM_ATTN (2*AT_STG)       // 40960

__global__ __launch_bounds__(256, 2) void attn_mma_kernel(
    const __half* __restrict__ a1p, const __half* __restrict__ a2p)
{
    extern __shared__ __align__(16) unsigned char smem[];
    const int ks  = blockIdx.x;
    const int cls = blockIdx.y;
    const int b   = blockIdx.z;
    const int tid = threadIdx.x;
    const int lane = tid & 31, wid = tid >> 5;
    const int wm = wid & 3, wn = wid >> 2;
    const uint32_t sb = smem_u32(smem);

    const size_t cbase = ((size_t)b*CC_*9 + cls)*4096 + ks*1024;
    const __half* A_g = a2p + cbase;
    const __half* B_g = a1p + cbase;

    int sdst[2];
    size_t ssrc[2];
#pragma unroll
    for (int i = 0; i < 2; i++) {
        int slot = tid + i*256;            // < 512
        int r = slot >> 2, q = slot & 3;
        sdst[i] = r*AT_STRIDE + q*16;
        ssrc[i] = (size_t)r*36864 + q*8;
    }

    float acc[2][8][4];
#pragma unroll
    for (int mh = 0; mh < 2; mh++)
#pragma unroll
        for (int nj = 0; nj < 8; nj++)
#pragma unroll
            for (int t = 0; t < 4; t++) acc[mh][nj][t] = 0.f;

    auto loadAB = [&](int c) {
        const uint32_t stg = sb + (c & 1)*AT_STG;
        const int kofs = c*32;
#pragma unroll
        for (int i = 0; i < 2; i++) {
            cp16(stg + sdst[i],            A_g + ssrc[i] + kofs);
            cp16(stg + AT_BYTES + sdst[i], B_g + ssrc[i] + kofs);
        }
        cp_commit();
    };

    loadAB(0);
    for (int c = 0; c < 32; c++) {
        cp_wait0();
        __syncthreads();
        if (c < 31) loadAB(c + 1);

        const uint32_t stg = sb + (c & 1)*AT_STG;
        const uint32_t A_s = stg;
        const uint32_t B_s = stg + AT_BYTES;
#pragma unroll
        for (int st = 0; st < 2; st++) {
            unsigned Af[2][4], Bf[4][4];
#pragma unroll
            for (int mh = 0; mh < 2; mh++) {
                uint32_t off = (uint32_t)(wm*32 + mh*16 + (lane & 15))*AT_STRIDE
                             + ((lane >> 4) << 4) + st*32;
                ldsm4(Af[mh], A_s + off);
            }
#pragma unroll
            for (int ng = 0; ng < 4; ng++) {
                uint32_t off = (uint32_t)(wn*64 + ng*16 + (lane & 7)
                             + ((lane >> 3) & 1)*8)*AT_STRIDE
                             + st*32 + ((lane >> 4) & 1)*16;
                ldsm4(Bf[ng], B_s + off);
            }
#pragma unroll
            for (int mh = 0; mh < 2; mh++)
#pragma unroll
                for (int ng = 0; ng < 4; ng++)
#pragma unroll
                    for (int s2 = 0; s2 < 2; s2++)
                        mma_f16_2(acc[mh][ng*2 + s2], Af[mh],
                                  Bf[ng][s2], Bf[ng][s2 + 2]);
        }
    }

#pragma unroll
    for (int mh = 0; mh < 2; mh++) {
        int o0 = wm*32 + mh*16 + (lane >> 2);
#pragma unroll
        for (int nj = 0; nj < 8; nj++) {
            int n0 = wn*64 + nj*8 + (lane & 3)*2;
            size_t r0 = ((size_t)b*CC_ + o0)*KK;
            size_t r1 = ((size_t)b*CC_ + o0 + 8)*KK;
            atomicAdd(&g_attn[r0 + (size_t)n0*9 + cls],       acc[mh][nj][0]);
            atomicAdd(&g_attn[r0 + (size_t)(n0 + 1)*9 + cls], acc[mh][nj][1]);
            atomicAdd(&g_attn[r1 + (size_t)n0*9 + cls],       acc[mh][nj][2]);
            atomicAdd(&g_attn[r1 + (size_t)(n0 + 1)*9 + cls], acc[mh][nj][3]);
        }
    }
}

// ---------------- softmax; emits dynamic kernels as fp16, permuted k ----------
__global__ __launch_bounds__(256) void softmax_kernel() {
    __shared__ float red[256];
    const int row = blockIdx.x;
    const float* rp = g_attn + (size_t)row*KK;
    const float scale = 0.029462782549439483f;
    const int tid = threadIdx.x;

    float m = -1e30f;
    for (int e = tid; e < KK; e += 256) m = fmaxf(m, rp[e]);
    red[tid] = m; __syncthreads();
    for (int s = 128; s > 0; s >>= 1) {
        if (tid < s) red[tid] = fmaxf(red[tid], red[tid + s]);
        __syncthreads();
    }
    m = red[0] * scale;
    __syncthreads();

    float sum = 0.f;
    for (int e = tid; e < KK; e += 256) sum += expf(rp[e]*scale - m);
    red[tid] = sum; __syncthreads();
    for (int s = 128; s > 0; s >>= 1) {
        if (tid < s) red[tid] += red[tid + s];
        __syncthreads();
    }
    float inv = 1.f / red[0];

    for (int e = tid; e < KK; e += 256) {
        float p = expf(rp[e]*scale - m) * inv;
        int i = e / 9, rr = e - i*9;
        int knew = rr*128 + i;
        g_k[(size_t)row*KK + knew] = __float2half(p);
    }
}

// ---------------- BN stats over av partitioned by (group, parity) ------------
__global__ __launch_bounds__(256) void stats_kernel() {
    const int g = blockIdx.x;
    const int b = blockIdx.y;
    const int tid = threadIdx.x;
    float s00=0,s01=0,s10=0,s11=0,q00=0,q01=0,q10=0,q11=0;
    for (int c = 0; c < 4; c++) {
        const float* p = g_av + ((size_t)b*CC_ + g*4 + c)*HW;
        for (int e = tid; e < HW/2; e += 256) {
            int y = e / 96;
            int x2 = (e - y*96) * 2;
            float v0 = p[y*WW + x2];
            float v1 = p[y*WW + x2 + 1];
            if (y & 1) { s10 += v0; q10 += v0*v0; s11 += v1; q11 += v1*v1; }
            else       { s00 += v0; q00 += v0*v0; s01 += v1; q01 += v1*v1; }
        }
    }
    __shared__ float red[256];
    float vals[8] = {s00, s01, s10, s11, q00, q01, q10, q11};
#pragma unroll
    for (int v = 0; v < 8; v++) {
        red[tid] = vals[v]; __syncthreads();
        for (int st = 128; st > 0; st >>= 1) {
            if (tid < st) red[tid] += red[tid + st];
            __syncthreads();
        }
        if (tid == 0) {
            int p2 = v & 3;
            if (v < 4) atomicAdd(&g_sum[g*4 + p2],   red[0]);
            else       atomicAdd(&g_sumsq[g*4 + p2], red[0]);
        }
        __syncthreads();
    }
}

__global__ void finalize_kernel() {
    int c = threadIdx.x;
    if (c < CC_) {
        float n = (float)STAT_N;
        float mean = g_sum[c] / n;
        float var  = g_sumsq[c] / n - mean*mean;
        g_mean[c] = mean;
        g_inv[c]  = NORM_SCALE * rsqrtf(var + EPSV);
    }
}

// ---------------- fused stack-gather + BN + residual epilogue ----------------
__global__ __launch_bounds__(256) void output_kernel(const float* __restrict__ x,
                                                     const float* __restrict__ mom_p,
                                                     float* __restrict__ out) {
    const float mom = *mom_p;
    for (size_t idx = (size_t)blockIdx.x*blockDim.x + threadIdx.x; idx < (size_t)TOT;
         idx += (size_t)gridDim.x*blockDim.x) {
        size_t b = idx / CHW;
        int r  = (int)(idx - b*CHW);
        int c2 = r / HW;
        int rr = r - c2*HW;
        int Y = rr / WW, X = rr - Y*WW;
        int i2 = (Y >= 96), j2 = (X >= 96);
        int ph = Y - i2*96, pw = X - j2*96;
        int sc = (c2 & ~3) | (i2*2 + j2);
        int sy = ph*2 + ((c2 >> 1) & 1);
        int sx = pw*2 + (c2 & 1);
        float v = g_av[((size_t)b*CC_ + sc)*HW + (size_t)sy*WW + sx];
        out[idx] = mom * x[idx] + (v - g_mean[c2]) * g_inv[c2];
    }
}

// ---------------- launch -----------------------------------------------------
extern "C" void kernel_launch(void* const* d_in, const int* in_sizes, int n_in,
                              void* d_out, int out_size) {
    const float* x   = (const float*)d_in[0];
    const float* w1  = (const float*)d_in[1];
    const float* w2  = (const float*)d_in[2];
    const float* w3  = (const float*)d_in[3];
    const float* mom = (const float*)d_in[4];
    float* out = (float*)d_out;

    cudaFuncSetAttribute(conv_mma_kernel,
                         cudaFuncAttributeMaxDynamicSharedMemorySize, SMEM_CONV);
    cudaFuncSetAttribute(attn_mma_kernel,
                         cudaFuncAttributeMaxDynamicSharedMemorySize, SMEM_ATTN);

    __half *pxe, *pxo, *pae, *pao, *a1p, *a2p, *w, *k;
    float *av;
    cudaGetSymbolAddress((void**)&pxe, g_pxe);
    cudaGetSymbolAddress((void**)&pxo, g_pxo);
    cudaGetSymbolAddress((void**)&pae, g_pae);
    cudaGetSymbolAddress((void**)&pao, g_pao);
    cudaGetSymbolAddress((void**)&a1p, g_a1p);
    cudaGetSymbolAddress((void**)&a2p, g_a2p);
    cudaGetSymbolAddress((void**)&av,  g_av);
    cudaGetSymbolAddress((void**)&w,   g_w);
    cudaGetSymbolAddress((void**)&k,   g_k);

    zero_kernel<<<2048, 256>>>();
    split_x_pad_kernel<<<8192, 256>>>(x);
    split_w_kernel<<<dim3(144, 3), 256>>>(w1, w2, w3);

    dim3 cgrid(HH, BB);   // full row per CTA
    conv_mma_kernel<<<cgrid, 256, SMEM_CONV>>>(pxe, pxo,
        w + 0*(size_t)CC_*KK, 0, a1p, nullptr, 2);
    conv_mma_kernel<<<cgrid, 256, SMEM_CONV>>>(pxe, pxo,
        w + 1*(size_t)CC_*KK, 0, a2p, nullptr, 2);
    conv_mma_kernel<<<cgrid, 256, SMEM_CONV>>>(pxe, pxo,
        w + 2*(size_t)CC_*KK, 0, pae, pao, 1);

    attn_mma_kernel<<<dim3(4, 9, BB), 256, SMEM_ATTN>>>(a1p, a2p);
    softmax_kernel<<<BB*CC_, 256>>>();

    conv_mma_kernel<<<cgrid, 256, SMEM_CONV>>>(pae, pao,
        k, (long)CC_*KK, av, nullptr, 0);

    stats_kernel<<<dim3(32, 8), 256>>>();
    finalize_kernel<<<1, 128>>>();
    output_kernel<<<8192, 256>>>(x, mom, out);
}

// round 17
// speedup vs baseline: 1.1507x; 1.1507x over previous
#include <cuda_runtime.h>
#include <cuda_fp16.h>
#include <cstdint>

#define BB 8
#define CC_ 128
#define HH 192
#define WW 192
#define HW (HH*WW)
#define CHW (CC_*HW)
#define TOT (BB*CHW)
#define KK 1152            // C*9
#define EPSV 1e-5f
#define NORM_SCALE 0.1816f
#define STAT_N (BB*4*(HH/2)*(WW/2))   // 294912

// padded image geometry (1-px halo + alignment tail)
#define WP 200
#define HP 194
#define PLANE (HP*WP)          // 38800
#define PCHW (CC_*PLANE)
#define PTOT (BB*PCHW)

// ---------------- scratch (device globals; no allocations allowed) ------------
__device__ __align__(16) __half g_pxe[PTOT];     // input, aligned shift (dx 0/2)
__device__ __align__(16) __half g_pxo[PTOT];     // input, odd shift (dx 1)
__device__ __align__(16) __half g_pae[PTOT];     // a3, aligned
__device__ __align__(16) __half g_pao[PTOT];     // a3, odd
// parity-packed conv outputs: [b][ch][class(9)][4096]
__device__ __align__(16) __half g_a1p[TOT];
__device__ __align__(16) __half g_a2p[TOT];
__device__ float g_avs[TOT];               // av in STACKED layout [b][c2][Y][X]
__device__ __align__(16) __half g_w[3*CC_*KK];   // [w][o][knew], knew=(r*3+dx)*128+ic
__device__ __align__(16) __half g_k[BB*CC_*KK];  // [b][o][knew]
__device__ float g_attn[BB*CC_*KK];        // [b][o][i*9+class]
__device__ float g_sum[CC_];
__device__ float g_sumsq[CC_];
__device__ float g_mean[CC_];
__device__ float g_inv[CC_];

// ---------------- PTX helpers -------------------------------------------------
__device__ __forceinline__ uint32_t smem_u32(const void* p) {
    uint32_t a;
    asm("{ .reg .u64 t; cvta.to.shared.u64 t, %1; cvt.u32.u64 %0, t; }"
        : "=r"(a) : "l"(p));
    return a;
}
__device__ __forceinline__ void ldsm4(unsigned* r, uint32_t addr) {
    asm volatile("ldmatrix.sync.aligned.m8n8.x4.shared.b16 {%0,%1,%2,%3}, [%4];"
                 : "=r"(r[0]), "=r"(r[1]), "=r"(r[2]), "=r"(r[3]) : "r"(addr));
}
__device__ __forceinline__ void ldsm4t(unsigned* r, uint32_t addr) {
    asm volatile("ldmatrix.sync.aligned.m8n8.x4.trans.shared.b16 {%0,%1,%2,%3}, [%4];"
                 : "=r"(r[0]), "=r"(r[1]), "=r"(r[2]), "=r"(r[3]) : "r"(addr));
}
__device__ __forceinline__ void mma_f16(float* d, const unsigned* a, const unsigned* b) {
    asm volatile(
        "mma.sync.aligned.m16n8k16.row.col.f32.f16.f16.f32 "
        "{%0,%1,%2,%3}, {%4,%5,%6,%7}, {%8,%9}, {%0,%1,%2,%3};"
        : "+f"(d[0]), "+f"(d[1]), "+f"(d[2]), "+f"(d[3])
        : "r"(a[0]), "r"(a[1]), "r"(a[2]), "r"(a[3]), "r"(b[0]), "r"(b[1]));
}
__device__ __forceinline__ void mma_f16_2(float* d, const unsigned* a,
                                          unsigned b0, unsigned b1) {
    asm volatile(
        "mma.sync.aligned.m16n8k16.row.col.f32.f16.f16.f32 "
        "{%0,%1,%2,%3}, {%4,%5,%6,%7}, {%8,%9}, {%0,%1,%2,%3};"
        : "+f"(d[0]), "+f"(d[1]), "+f"(d[2]), "+f"(d[3])
        : "r"(a[0]), "r"(a[1]), "r"(a[2]), "r"(a[3]), "r"(b0), "r"(b1));
}
__device__ __forceinline__ void cp16(uint32_t dst, const void* src) {
    asm volatile("cp.async.cg.shared.global [%0], [%1], 16;"
                 :: "r"(dst), "l"(src) : "memory");
}
__device__ __forceinline__ void cp4(uint32_t dst, const void* src) {
    asm volatile("cp.async.ca.shared.global [%0], [%1], 4;"
                 :: "r"(dst), "l"(src) : "memory");
}
__device__ __forceinline__ void cp_commit() {
    asm volatile("cp.async.commit_group;" ::: "memory");
}
__device__ __forceinline__ void cp_wait1() {
    asm volatile("cp.async.wait_group 1;" ::: "memory");
}
__device__ __forceinline__ void cp_wait0() {
    asm volatile("cp.async.wait_group 0;" ::: "memory");
}

// ---------------- zero accumulators + padded-array halos ----------------------
__global__ void zero_kernel() {
    int n = BB*CC_*KK;
    for (int i = blockIdx.x*blockDim.x + threadIdx.x; i < n; i += gridDim.x*blockDim.x)
        g_attn[i] = 0.f;
    const __half z = __float2half(0.f);
    int hn = BB*CC_*2128;
    for (int idx = blockIdx.x*blockDim.x + threadIdx.x; idx < hn;
         idx += gridDim.x*blockDim.x) {
        int plane = idx / 2128, e = idx - plane*2128;
        int row, px;
        if (e < 400) { row = (e < 200) ? 0 : 193; px = (e < 200) ? e : e - 200; }
        else { int e2 = e - 400; row = 1 + e2/9; int i9 = e2 - (e2/9)*9;
               px = (i9 < 2) ? i9 : 191 + i9; }
        size_t off = (size_t)plane*PLANE + row*WP + px;
        g_pae[off] = z; g_pao[off] = z;
    }
    if (blockIdx.x == 0 && threadIdx.x < CC_) {
        g_sum[threadIdx.x] = 0.f;
        g_sumsq[threadIdx.x] = 0.f;
    }
}

// ---------------- pad x into fp16 copies (aligned + shifted) ------------------
__global__ void split_x_pad_kernel(const float* __restrict__ x) {
    for (size_t idx = (size_t)blockIdx.x*blockDim.x + threadIdx.x; idx < (size_t)PTOT;
         idx += (size_t)gridDim.x*blockDim.x) {
        size_t bc = idx / PLANE;
        int p  = (int)(idx - bc*PLANE);
        int py = p / WP, px = p - py*WP;
        int yy = py - 1;
        float va = 0.f, vs = 0.f;
        if ((unsigned)yy < HH) {
            const float* row = x + bc*HW + (size_t)yy*WW;
            int xa = px - 1, xs = px - 2;
            if ((unsigned)xa < WW) va = row[xa];
            if ((unsigned)xs < WW) vs = row[xs];
        }
        g_pxe[idx] = __float2half(va);
        g_pxo[idx] = __float2half(vs);
    }
}

// ---------------- convert static weights (permuted k: knew=(r*3+dx)*128+ic) ---
__global__ void split_w_kernel(const float* __restrict__ w1,
                               const float* __restrict__ w2,
                               const float* __restrict__ w3) {
    const float* w = (blockIdx.y == 0) ? w1 : (blockIdx.y == 1) ? w2 : w3;
    int base = blockIdx.y * CC_ * KK;
    for (int e = blockIdx.x*blockDim.x + threadIdx.x; e < CC_*KK;
         e += gridDim.x*blockDim.x) {
        int o = e / KK, knew = e - o*KK;
        int rr = knew >> 7, ic = knew & 127;
        g_w[base + e] = __float2half(w[(size_t)o*KK + ic*9 + rr]);
    }
}

// ---------------- fp16 tensor-core implicit-GEMM 3x3 conv ---------------------
// CTA: M=128 o x N=96 px. K=1152 in 36 chunks of 32, (r,dx)-major.
// Single fp16 product. 3-stage cp.async pipeline.
// Modes: 0 stacked-layout fp32 out (avs); 1 padded planes; 2 parity-packed.
#define A_STRIDE 80
#define B_STRIDE 208
#define A_BYTES (128*A_STRIDE)
#define B_BYTES (32*B_STRIDE)
#define STG (A_BYTES + B_BYTES)       // 16896
#define SMEM_CONV (3*STG)             // 50688

__global__ __launch_bounds__(256, 2) void conv_mma_kernel(
    const __half* __restrict__ pe, const __half* __restrict__ po,
    const __half* __restrict__ w_g, long wbstride,
    void* __restrict__ p0, void* __restrict__ p1, int mode)
{
    extern __shared__ __align__(16) unsigned char smem[];
    const int b  = blockIdx.z;
    const int y  = blockIdx.y;
    const int x0 = blockIdx.x * 96;
    const int tid = threadIdx.x;
    const int lane = tid & 31, wid = tid >> 5;
    const int wm = wid & 3, wn = wid >> 2;
    const uint32_t sb = smem_u32(smem);

    const __half* peb = pe + (size_t)b*PCHW;
    const __half* pob = po + (size_t)b*PCHW;
    const __half* wg = w_g + (size_t)b*wbstride;

    int bsrc[6], bdst[6];
#pragma unroll
    for (int i = 0; i < 6; i++) {
        int slot = tid + i*256;              // < 1536
        int rowt = slot / 48, np = slot - rowt*48;
        bsrc[i] = rowt*PLANE + np*2;
        bdst[i] = rowt*B_STRIDE + np*4;
    }
    int adst[2], aoff[2];
#pragma unroll
    for (int i = 0; i < 2; i++) {
        int slot = tid + i*256;              // < 512
        int o = slot >> 2, qq = slot & 3;
        adst[i] = o*A_STRIDE + qq*16;
        aoff[i] = o*KK + qq*8;
    }

    float acc[2][6][4];
#pragma unroll
    for (int mh = 0; mh < 2; mh++)
#pragma unroll
        for (int j = 0; j < 6; j++)
#pragma unroll
            for (int t = 0; t < 4; t++) acc[mh][j][t] = 0.f;

    auto loadAB = [&](int c) {
        const uint32_t stg = sb + (c % 3)*STG;
        const int kofs = c*32;
#pragma unroll
        for (int i = 0; i < 2; i++) cp16(stg + adst[i], wg + aoff[i] + kofs);
        int r = c / 12, t = c - r*12;
        int dx = t >> 2, q = t & 3;
        int ibase = q*32*PLANE + (y + r)*WP + x0 + dx + (dx == 1);
        const __half* hp = ((dx == 1) ? pob : peb) + ibase;
        const uint32_t bb = stg + A_BYTES;
#pragma unroll
        for (int i = 0; i < 6; i++)
            cp4(bb + bdst[i], hp + bsrc[i]);
        cp_commit();
    };

    loadAB(0);
    loadAB(1);

    for (int c = 0; c < 36; c++) {
        if (c < 34) cp_wait1(); else cp_wait0();
        __syncthreads();
        if (c < 34) loadAB(c + 2);

        const uint32_t stg = sb + (c % 3)*STG;
        const uint32_t A_s = stg;
        const uint32_t B_s = stg + A_BYTES;
#pragma unroll
        for (int st = 0; st < 2; st++) {
            unsigned Af[2][4], Bf[3][4];
#pragma unroll
            for (int mh = 0; mh < 2; mh++) {
                uint32_t off = (uint32_t)(wm*32 + mh*16 + (lane & 15))*A_STRIDE
                             + ((lane >> 4) << 4) + st*32;
                ldsm4(Af[mh], A_s + off);
            }
#pragma unroll
            for (int nf = 0; nf < 3; nf++) {
                uint32_t off = (uint32_t)(st*16 + (lane & 15))*B_STRIDE
                             + wn*96 + nf*32 + ((lane >> 4) << 4);
                ldsm4t(Bf[nf], B_s + off);
            }
#pragma unroll
            for (int mh = 0; mh < 2; mh++)
#pragma unroll
                for (int j = 0; j < 6; j++)
                    mma_f16(acc[mh][j], Af[mh], &Bf[j >> 1][(j & 1)*2]);
        }
    }

    // ---- epilogue ----
    if (mode == 0) {
        // write stacked layout: c2=(o&~3)|((y&1)<<1)|(x&1),
        // Y=((o>>1)&1)*96 + (y>>1), X=(o&1)*96 + (x>>1).
        // de-interleave via smem in two 64-channel halves.
        float* avs = (float*)p0;
        float* sf = (float*)smem;        // [64][2][96] fp32 = 49152 B
        const int yp2 = (y & 1) << 1;
        const int Ybase = y >> 1;
#pragma unroll
        for (int half = 0; half < 2; half++) {
            __syncthreads();
            // stage: this half's channels (wm in {2*half, 2*half+1})
#pragma unroll
            for (int mh = 0; mh < 2; mh++) {
                int o = wm*32 + mh*16 + (lane >> 2);
                if ((wm >> 1) == half) {
                    int ol = o - half*64;
#pragma unroll
                    for (int j = 0; j < 6; j++) {
                        int xh = wn*24 + j*4 + (lane & 3);  // x>>1 within tile
#pragma unroll
                        for (int t = 0; t < 4; t++) {
                            int oo = ol + (t >> 1)*8;
                            sf[(oo*2 + (t & 1))*96 + xh] = acc[mh][j][t];
                        }
                    }
                }
            }
            __syncthreads();
            // store: 128 runs (64 ch x 2 parity) of 96 contiguous floats
            for (int run = wid; run < 128; run += 8) {
                int ol = run >> 1, p = run & 1;
                int o = half*64 + ol;
                int c2 = (o & ~3) | yp2 | p;
                int Y = ((o >> 1) & 1)*96 + Ybase;
                int Xb = (o & 1)*96 + (x0 >> 1);
                float* dst = avs + ((size_t)b*CC_ + c2)*HW + (size_t)Y*WW + Xb;
                const float* src = sf + (ol*2 + p)*96;
                for (int e = lane; e < 48; e += 32)
                    dst[e] = src[e];
            }
        }
    } else if (mode == 1) {
        // stage plane, stride 100 per ch, +1 element shift
        __syncthreads();
        __half* sh = (__half*)smem;      // 128*100
#pragma unroll
        for (int mh = 0; mh < 2; mh++) {
            int o = wm*32 + mh*16 + (lane >> 2);
#pragma unroll
            for (int j = 0; j < 6; j++) {
                int xb = wn*48 + j*8 + (lane & 3)*2;
#pragma unroll
                for (int t = 0; t < 4; t++) {
                    int oo = o + (t >> 1)*8;
                    int xx = xb + (t & 1);
                    sh[oo*100 + xx + 1] = __float2half(acc[mh][j][t]);
                }
            }
        }
        __syncthreads();
        __half* eh = (__half*)p0;   // pae
        __half* oh = (__half*)p1;   // pao
        for (int run = wid; run < 256; run += 8) {
            int a = run >> 7, ch = run & 127;
            const __half* sp = sh + ch*100;
            __half* base = (a == 0) ? eh : oh;
            __half* dst = base + ((size_t)b*CC_ + ch)*PLANE
                        + (size_t)(y + 1)*WP + x0 + 1 + a;
            if (a == 0) {
                if (lane == 0) dst[0]  = sp[1];
                if (lane == 1) dst[95] = sp[96];
                for (int j2 = lane; j2 < 47; j2 += 32) {
                    uint32_t v = *(const uint32_t*)(sp + 2 + 2*j2);
                    *(uint32_t*)(dst + 1 + 2*j2) = v;
                }
            } else {
                for (int j2 = lane; j2 < 48; j2 += 32) {
                    uint32_t lo2 = (uint32_t)*(const unsigned short*)(sp + 1 + 2*j2);
                    uint32_t hi2 = (uint32_t)*(const unsigned short*)(sp + 2 + 2*j2);
                    *(uint32_t*)(dst + 2*j2) = lo2 | (hi2 << 16);
                }
            }
        }
    } else {
        // parity-packed: stage [ch][cx*32+qx] plane, then uint4 stores
        __syncthreads();
        __half* sh = (__half*)smem;      // 128*96
#pragma unroll
        for (int mh = 0; mh < 2; mh++) {
            int o = wm*32 + mh*16 + (lane >> 2);
#pragma unroll
            for (int j = 0; j < 6; j++) {
                int xb = wn*48 + j*8 + (lane & 3)*2;
#pragma unroll
                for (int t = 0; t < 4; t++) {
                    int oo = o + (t >> 1)*8;
                    int xx = xb + (t & 1);
                    int qx = xx / 3;
                    int cx = xx - qx*3;
                    sh[oo*96 + cx*32 + qx] = __float2half(acc[mh][j][t]);
                }
            }
        }
        __syncthreads();
        __half* ph = (__half*)p0;
        int cy = y % 3, qy = y / 3;
        int bx32 = blockIdx.x * 32;
#pragma unroll
        for (int i = 0; i < 6; i++) {
            int s = tid + i*256;      // < 1536
            int seg = s >> 2, q = s & 3;
            int ch = seg / 3, cx = seg - ch*3;
            const uint4* src = (const uint4*)(sh + ch*96 + cx*32 + q*8);
            __half* dst = ph
                + (((size_t)b*CC_ + ch)*9 + cy*3 + cx)*4096 + qy*64 + bx32 + q*8;
            *(uint4*)dst = *src;
        }
    }
}

// ---------------- tensor-core attention correlation GEMM ----------------------
// Single fp16 product. M=128(o) x N=128(i), K slab 1024.
#define AT_STRIDE 80
#define AT_BYTES (128*AT_STRIDE)   // 10240
#define AT_STG (2*AT_BYTES)        // 20480
#define SMEM_ATTN (2*AT_STG)       // 40960

__global__ __launch_bounds__(256, 2) void attn_mma_kernel(
    const __half* __restrict__ a1p, const __half* __restrict__ a2p)
{
    extern __shared__ __align__(16) unsigned char smem[];
    const int ks  = blockIdx.x;
    const int cls = blockIdx.y;
    const int b   = blockIdx.z;
    const int tid = threadIdx.x;
    const int lane = tid & 31, wid = tid >> 5;
    const int wm = wid & 3, wn = wid >> 2;
    const uint32_t sb = smem_u32(smem);

    const size_t cbase = ((size_t)b*CC_*9 + cls)*4096 + ks*1024;
    const __half* A_g = a2p + cbase;
    const __half* B_g = a1p + cbase;

    int sdst[2];
    size_t ssrc[2];
#pragma unroll
    for (int i = 0; i < 2; i++) {
        int slot = tid + i*256;            // < 512
        int r = slot >> 2, q = slot & 3;
        sdst[i] = r*AT_STRIDE + q*16;
        ssrc[i] = (size_t)r*36864 + q*8;
    }

    float acc[2][8][4];
#pragma unroll
    for (int mh = 0; mh < 2; mh++)
#pragma unroll
        for (int nj = 0; nj < 8; nj++)
#pragma unroll
            for (int t = 0; t < 4; t++) acc[mh][nj][t] = 0.f;

    auto loadAB = [&](int c) {
        const uint32_t stg = sb + (c & 1)*AT_STG;
        const int kofs = c*32;
#pragma unroll
        for (int i = 0; i < 2; i++) {
            cp16(stg + sdst[i],            A_g + ssrc[i] + kofs);
            cp16(stg + AT_BYTES + sdst[i], B_g + ssrc[i] + kofs);
        }
        cp_commit();
    };

    loadAB(0);
    for (int c = 0; c < 32; c++) {
        cp_wait0();
        __syncthreads();
        if (c < 31) loadAB(c + 1);

        const uint32_t stg = sb + (c & 1)*AT_STG;
        const uint32_t A_s = stg;
        const uint32_t B_s = stg + AT_BYTES;
#pragma unroll
        for (int st = 0; st < 2; st++) {
            unsigned Af[2][4], Bf[4][4];
#pragma unroll
            for (int mh = 0; mh < 2; mh++) {
                uint32_t off = (uint32_t)(wm*32 + mh*16 + (lane & 15))*AT_STRIDE
                             + ((lane >> 4) << 4) + st*32;
                ldsm4(Af[mh], A_s + off);
            }
#pragma unroll
            for (int ng = 0; ng < 4; ng++) {
                uint32_t off = (uint32_t)(wn*64 + ng*16 + (lane & 7)
                             + ((lane >> 3) & 1)*8)*AT_STRIDE
                             + st*32 + ((lane >> 4) & 1)*16;
                ldsm4(Bf[ng], B_s + off);
            }
#pragma unroll
            for (int mh = 0; mh < 2; mh++)
#pragma unroll
                for (int ng = 0; ng < 4; ng++)
#pragma unroll
                    for (int s2 = 0; s2 < 2; s2++)
                        mma_f16_2(acc[mh][ng*2 + s2], Af[mh],
                                  Bf[ng][s2], Bf[ng][s2 + 2]);
        }
    }

#pragma unroll
    for (int mh = 0; mh < 2; mh++) {
        int o0 = wm*32 + mh*16 + (lane >> 2);
#pragma unroll
        for (int nj = 0; nj < 8; nj++) {
            int n0 = wn*64 + nj*8 + (lane & 3)*2;
            size_t r0 = ((size_t)b*CC_ + o0)*KK;
            size_t r1 = ((size_t)b*CC_ + o0 + 8)*KK;
            atomicAdd(&g_attn[r0 + (size_t)n0*9 + cls],       acc[mh][nj][0]);
            atomicAdd(&g_attn[r0 + (size_t)(n0 + 1)*9 + cls], acc[mh][nj][1]);
            atomicAdd(&g_attn[r1 + (size_t)n0*9 + cls],       acc[mh][nj][2]);
            atomicAdd(&g_attn[r1 + (size_t)(n0 + 1)*9 + cls], acc[mh][nj][3]);
        }
    }
}

// ---------------- softmax; emits dynamic kernels as fp16, permuted k ----------
__global__ __launch_bounds__(256) void softmax_kernel() {
    __shared__ float red[256];
    const int row = blockIdx.x;
    const float* rp = g_attn + (size_t)row*KK;
    const float scale = 0.029462782549439483f;
    const int tid = threadIdx.x;

    float m = -1e30f;
    for (int e = tid; e < KK; e += 256) m = fmaxf(m, rp[e]);
    red[tid] = m; __syncthreads();
    for (int s = 128; s > 0; s >>= 1) {
        if (tid < s) red[tid] = fmaxf(red[tid], red[tid + s]);
        __syncthreads();
    }
    m = red[0] * scale;
    __syncthreads();

    float sum = 0.f;
    for (int e = tid; e < KK; e += 256) sum += expf(rp[e]*scale - m);
    red[tid] = sum; __syncthreads();
    for (int s = 128; s > 0; s >>= 1) {
        if (tid < s) red[tid] += red[tid + s];
        __syncthreads();
    }
    float inv = 1.f / red[0];

    for (int e = tid; e < KK; e += 256) {
        float p = expf(rp[e]*scale - m) * inv;
        int i = e / 9, rr = e - i*9;
        int knew = rr*128 + i;
        g_k[(size_t)row*KK + knew] = __float2half(p);
    }
}

// ---------------- BN stats over stacked avs (contiguous per channel) ----------
__global__ __launch_bounds__(256) void stats_kernel() {
    const int c2 = blockIdx.x;    // stat channel, direct
    const int b  = blockIdx.y;
    const int tid = threadIdx.x;
    const float* p = g_avs + ((size_t)b*CC_ + c2)*HW;
    float s = 0.f, q = 0.f;
    for (int e = tid; e < HW; e += 256) {
        float v = p[e];
        s += v; q += v*v;
    }
    __shared__ float red[512];
    red[tid] = s; red[tid + 256] = q;
    __syncthreads();
    for (int st = 128; st > 0; st >>= 1) {
        if (tid < st) {
            red[tid] += red[tid + st];
            red[tid + 256] += red[tid + 256 + st];
        }
        __syncthreads();
    }
    if (tid == 0) {
        atomicAdd(&g_sum[c2],   red[0]);
        atomicAdd(&g_sumsq[c2], red[256]);
    }
}

__global__ void finalize_kernel() {
    int c = threadIdx.x;
    if (c < CC_) {
        float n = (float)STAT_N;
        float mean = g_sum[c] / n;
        float var  = g_sumsq[c] / n - mean*mean;
        g_mean[c] = mean;
        g_inv[c]  = NORM_SCALE * rsqrtf(var + EPSV);
    }
}

// ---------------- streaming BN + residual epilogue (avs is pre-stacked) -------
__global__ __launch_bounds__(256) void output_kernel(const float* __restrict__ x,
                                                     const float* __restrict__ mom_p,
                                                     float* __restrict__ out) {
    const float mom = *mom_p;
    for (size_t idx4 = (size_t)blockIdx.x*blockDim.x + threadIdx.x; idx4 < (size_t)TOT/4;
         idx4 += (size_t)gridDim.x*blockDim.x) {
        size_t idx = idx4*4;
        int c2 = (int)((idx / HW) & 127);
        float mean = g_mean[c2], inv = g_inv[c2];
        float4 xv = *(const float4*)(x + idx);
        float4 av = *(const float4*)(g_avs + idx);
        float4 o;
        o.x = mom*xv.x + (av.x - mean)*inv;
        o.y = mom*xv.y + (av.y - mean)*inv;
        o.z = mom*xv.z + (av.z - mean)*inv;
        o.w = mom*xv.w + (av.w - mean)*inv;
        *(float4*)(out + idx) = o;
    }
}

// ---------------- launch -----------------------------------------------------
extern "C" void kernel_launch(void* const* d_in, const int* in_sizes, int n_in,
                              void* d_out, int out_size) {
    const float* x   = (const float*)d_in[0];
    const float* w1  = (const float*)d_in[1];
    const float* w2  = (const float*)d_in[2];
    const float* w3  = (const float*)d_in[3];
    const float* mom = (const float*)d_in[4];
    float* out = (float*)d_out;

    cudaFuncSetAttribute(conv_mma_kernel,
                         cudaFuncAttributeMaxDynamicSharedMemorySize, SMEM_CONV);
    cudaFuncSetAttribute(attn_mma_kernel,
                         cudaFuncAttributeMaxDynamicSharedMemorySize, SMEM_ATTN);

    __half *pxe, *pxo, *pae, *pao, *a1p, *a2p, *w, *k;
    float *avs;
    cudaGetSymbolAddress((void**)&pxe, g_pxe);
    cudaGetSymbolAddress((void**)&pxo, g_pxo);
    cudaGetSymbolAddress((void**)&pae, g_pae);
    cudaGetSymbolAddress((void**)&pao, g_pao);
    cudaGetSymbolAddress((void**)&a1p, g_a1p);
    cudaGetSymbolAddress((void**)&a2p, g_a2p);
    cudaGetSymbolAddress((void**)&avs, g_avs);
    cudaGetSymbolAddress((void**)&w,   g_w);
    cudaGetSymbolAddress((void**)&k,   g_k);

    zero_kernel<<<2048, 256>>>();
    split_x_pad_kernel<<<8192, 256>>>(x);
    split_w_kernel<<<dim3(144, 3), 256>>>(w1, w2, w3);

    dim3 cgrid(2, HH, BB);
    conv_mma_kernel<<<cgrid, 256, SMEM_CONV>>>(pxe, pxo,
        w + 0*(size_t)CC_*KK, 0, a1p, nullptr, 2);
    conv_mma_kernel<<<cgrid, 256, SMEM_CONV>>>(pxe, pxo,
        w + 1*(size_t)CC_*KK, 0, a2p, nullptr, 2);
    conv_mma_kernel<<<cgrid, 256, SMEM_CONV>>>(pxe, pxo,
        w + 2*(size_t)CC_*KK, 0, pae, pao, 1);

    attn_mma_kernel<<<dim3(4, 9, BB), 256, SMEM_ATTN>>>(a1p, a2p);
    softmax_kernel<<<BB*CC_, 256>>>();

    conv_mma_kernel<<<cgrid, 256, SMEM_CONV>>>(pae, pao,
        k, (long)CC_*KK, avs, nullptr, 0);

    stats_kernel<<<dim3(CC_, BB), 256>>>();
    finalize_kernel<<<1, 128>>>();
    output_kernel<<<4096, 256>>>(x, mom, out);
}